// round 16
// baseline (speedup 1.0000x reference)
#include <cuda_runtime.h>

#define N 768
#define D 512
#define NCAND ((N * (N - 1)) / 2)     // 294528 candidate i<j pairs
#define B2 592
#define T2 256
#define SLICE 498                     // candidates per block (592*498 >= NCAND)

// Scratch (no allocations allowed anywhere). Zero-initialized at load.
__device__ double g_part[B2];
__device__ int    g_pcnt[B2];
__device__ int    g_done;             // reset by finishing block each replay

__device__ __forceinline__ float fast_rcp(float x) {
    float r; asm("rcp.approx.f32 %0, %1;" : "=f"(r) : "f"(x)); return r;
}
__device__ __forceinline__ float fast_lg2(float x) {
    float r; asm("lg2.approx.f32 %0, %1;" : "=f"(r) : "f"(x)); return r;
}
__device__ __forceinline__ float fast_sqrt(float x) {
    float r; asm("sqrt.approx.f32 %0, %1;" : "=f"(r) : "f"(x)); return r;
}

// C(i) = number of i<j pairs with first index < i
__device__ __forceinline__ int trih(int i) { return (i * (2 * N - 1 - i)) >> 1; }

// ---------------------------------------------------------------------------
// Single fused kernel, no grid barrier, no global pair list:
//   phase 1: block filters its 498-candidate slice into a SMEM list
//   phase 2: block's 8 warps process matches round-robin (balanced)
//   tail:    acq_rel last-arriving-block deterministic finish (no spins)
// ---------------------------------------------------------------------------
__global__ void __launch_bounds__(T2, 4)
mls_fused(const float* __restrict__ muX,
          const float* __restrict__ lss,
          const void*  __restrict__ gty,
          float* __restrict__ out) {
    __shared__ double wsum[T2 / 32];
    __shared__ int    s_list[512];
    __shared__ int    s_n;
    __shared__ int    sh_last;

    int t    = threadIdx.x;
    int lane = t & 31;
    int wid  = t >> 5;

    // ---- label width detection (int64 vs int32), block-cooperative ----
    // gty values in [0,64). If little-endian int64, every odd 32-bit word of
    // the first N words is 0. Word 2*j <= 1534 is in-bounds for int64 layout;
    // N words in-bounds for int32.
    const int* gw = (const int*)gty;
    int flag = 0;
    if (t == 0) s_n = 0;
    #pragma unroll
    for (int k = 0; k < 3; k++) {
        int x = t + (k << 8);
        if ((x & 1) && __ldg(&gw[x]) != 0) flag = 1;
    }
    int is32 = __syncthreads_or(flag);   // also publishes s_n = 0

    // ---- phase 1: filter this block's candidate slice into smem ----
    int base = blockIdx.x * SLICE;
    #pragma unroll
    for (int k = 0; k < 2; k++) {
        int o = t + (k << 8);
        int c = base + o;
        if (o < SLICE && c < NCAND) {
            // decode c -> (i, j): closed form + BOUNDED fix-up.
            // disc = 1535^2 - 8c is an exact integer < 2^24; sqrt.approx is
            // within ~1 ulp so the i estimate is off by <= 2.
            float disc = (float)((2 * N - 1) * (2 * N - 1) - 8 * c);
            int i = (int)(((float)(2 * N - 1) - fast_sqrt(disc)) * 0.5f);
            if (i < 0) i = 0;
            if (i > N - 2) i = N - 2;
            #pragma unroll
            for (int f = 0; f < 3; f++) {
                if (i > 0 && trih(i) > c) --i;
                else if (i < N - 2 && trih(i + 1) <= c) ++i;
            }
            int j = i + 1 + (c - trih(i));
            int li = is32 ? __ldg(&gw[i]) : __ldg(&gw[2 * i]);
            int lj = is32 ? __ldg(&gw[j]) : __ldg(&gw[2 * j]);
            if (li == lj && j > i && j < N)
                s_list[atomicAdd(&s_n, 1)] = (i << 16) | j;
        }
    }
    __syncthreads();
    int np = s_n;

    // ---- phase 2: warps take the block's matches round-robin ----
    float accd = 0.0f;   // sum of d^2 / s
    float accl = 0.0f;   // sum of lg2(prod s)
    for (int p = wid; p < np; p += T2 / 32) {
        int pk = s_list[p];
        int pi = pk >> 16;
        int pj = pk & 0xFFFF;
        const float4* mi = (const float4*)(muX + (size_t)pi * D);
        const float4* mj = (const float4*)(muX + (size_t)pj * D);
        const float4* si = (const float4*)(lss + (size_t)pi * D);
        const float4* sj = (const float4*)(lss + (size_t)pj * D);

        // load both raw mu rows (4 float4 per lane per row); norms on the fly
        float4 va[4], vb[4];
        float ssa = 0.0f, ssb = 0.0f;
        #pragma unroll
        for (int k = 0; k < 4; k++) {
            int idx = lane + 32 * k;          // 128 float4 per row
            va[k] = mi[idx];
            vb[k] = mj[idx];
            ssa += va[k].x * va[k].x + va[k].y * va[k].y
                 + va[k].z * va[k].z + va[k].w * va[k].w;
            ssb += vb[k].x * vb[k].x + vb[k].y * vb[k].y
                 + vb[k].z * vb[k].z + vb[k].w * vb[k].w;
        }
        #pragma unroll
        for (int o = 16; o; o >>= 1) {
            ssa += __shfl_xor_sync(0xFFFFFFFFu, ssa, o);
            ssb += __shfl_xor_sync(0xFFFFFFFFu, ssb, o);
        }
        float rna = fast_rcp(fmaxf(fast_sqrt(ssa), 1e-12f));
        float rnb = fast_rcp(fmaxf(fast_sqrt(ssb), 1e-12f));

        #pragma unroll
        for (int k = 0; k < 4; k++) {
            int idx = lane + 32 * k;
            float4 la = si[idx];
            float4 lb = sj[idx];
            float d, s, prod;
            d = va[k].x * rna - vb[k].x * rnb;
            s = __expf(la.x) + __expf(lb.x);
            accd += d * d * fast_rcp(s); prod = s;
            d = va[k].y * rna - vb[k].y * rnb;
            s = __expf(la.y) + __expf(lb.y);
            accd += d * d * fast_rcp(s); prod *= s;
            d = va[k].z * rna - vb[k].z * rnb;
            s = __expf(la.z) + __expf(lb.z);
            accd += d * d * fast_rcp(s); prod *= s;
            d = va[k].w * rna - vb[k].w * rnb;
            s = __expf(la.w) + __expf(lb.w);
            accd += d * d * fast_rcp(s); prod *= s;
            accl += fast_lg2(prod);           // 1 lg2 per 4 elements
        }
    }

    // ---- warp reduce (float), block reduce (double), publish partial ----
    float val = accd + 0.69314718055994531f * accl;
    #pragma unroll
    for (int o = 16; o; o >>= 1) val += __shfl_xor_sync(0xFFFFFFFFu, val, o);
    if (lane == 0) wsum[wid] = (double)val;
    __syncthreads();
    if (t == 0) {
        double bs = 0.0;
        #pragma unroll
        for (int w = 0; w < T2 / 32; w++) bs += wsum[w];
        g_part[blockIdx.x] = bs;
        g_pcnt[blockIdx.x] = np;
        // acq_rel arrival: release orders our partial stores; acquire makes
        // earlier blocks' partials visible if we are last. Returns old count.
        int old;
        asm volatile("atom.acq_rel.gpu.global.add.s32 %0, [%1], %2;"
                     : "=r"(old) : "l"(&g_done), "r"(1) : "memory");
        sh_last = (old == B2 - 1) ? 1 : 0;
    }
    __syncthreads();

    // ---- LAST-ARRIVING block: deterministic final reduction + reset ----
    if (sh_last) {
        double a2 = 0.0;
        int    c2 = 0;
        for (int i = t; i < B2; i += T2) {     // bounded: 3 iterations
            a2 += __ldcg(&g_part[i]);
            c2 += __ldcg(&g_pcnt[i]);
        }
        #pragma unroll
        for (int o = 16; o; o >>= 1) {
            a2 += __shfl_xor_sync(0xFFFFFFFFu, a2, o);
            c2 += __shfl_xor_sync(0xFFFFFFFFu, c2, o);
        }
        if (lane == 0) { wsum[wid] = a2; ((int*)s_list)[wid] = c2; }
        __syncthreads();
        if (t == 0) {
            double s = 0.0;
            int    c = 0;
            #pragma unroll
            for (int w = 0; w < T2 / 32; w++) { s += wsum[w]; c += ((int*)s_list)[w]; }
            out[0] = c ? (float)(s / (double)c) : 0.0f;
            g_done = 0;                  // reset for next graph replay
        }
    }
}

extern "C" void kernel_launch(void* const* d_in, const int* in_sizes, int n_in,
                              void* d_out, int out_size) {
    const float* muX = (const float*)d_in[0];
    const float* lss = (const float*)d_in[1];
    const void*  gty = d_in[2];
    (void)in_sizes; (void)n_in; (void)out_size;

    mls_fused<<<B2, T2>>>(muX, lss, gty, (float*)d_out);
}